// round 13
// baseline (speedup 1.0000x reference)
#include <cuda_runtime.h>
#include <cstdint>

// ---- Problem constants ----
#define NBATCH    1024
#define NUM_VARS  2048
#define LEAVES    4096
#define LEVELS    12
#define WIDTH     4096
#define NODES     (LEVELS * WIDTH)          // 49152
#define NW_I      (NODES / 32)              // 1536
#define LVL_WORDS (WIDTH / 32)              // 128
#define NGROUPS_I (NW_I / 32)               // 48
#define LVBM_W    (NUM_VARS / 32)           // 64

// ---- Capacities (expected: ~160 interior, ~440 vars, <=91/level) ----
#define ICAP      768      // interior slots (overflow -> loud fail)
#define VCAP      1024     // gathered-var slots (overflow -> loud fail)
#define PROG_CAP  8192
#define LVL_CAP   512      // per-level worklist (overflow -> flag -> loud fail)

// ---- Eval config ----
#define EPB    4
#define TB_B   (EPB * 32)              // 128 threads
#define GRID_B (NBATCH / EPB)          // 256 CTAs

// ---- Device-global scratch ----
__device__ int  g_slot[NODES];
__device__ int4 g_prog[PROG_CAP];
__device__ int  g_varlist[NUM_VARS];
__device__ int  g_hdr[20];  // [0]=n_int [1..13]=prog offsets [14]=nv [15]=ovf

// Operand encoding:
//   ref < 4096 : leaf.  pos = ref>>1 into gathered vars; complement if (ref&1)
//   ref >= 4096: interior slot = ref - 4096
//   op (0=AND,1=OR) in bit 30 of .x

// ============================================================================
// Phase A (1 CTA): worklist reachability + var-list + compact program.
// Fused enumerate/expand: atomicOr-return dedup appends interior children to
// their level's worklist; leaf children mark the needed-var bitmap. One pass
// and one barrier per level.
// ============================================================================
__global__ void __launch_bounds__(1024, 1)
prune_kernel(const int4* __restrict__ child4,   // [NODES]
             const int*  __restrict__ op_type)  // [NODES]
{
    __shared__ uint32_t bm[NW_I];                    // 6 KB
    __shared__ int      pref[NW_I];                  // 6 KB
    __shared__ int      gsum[NGROUPS_I + 1];
    __shared__ int      lvl_list[LEVELS * LVL_CAP];  // 24 KB
    __shared__ int      nl[LEVELS];
    __shared__ uint32_t lvbm[LVBM_W];                // needed vars
    __shared__ int      lpref[LVBM_W + 1];
    __shared__ int      varpos[NUM_VARS];            // 8 KB
    __shared__ int      ovf;

    const int tid = threadIdx.x;

    for (int i = tid; i < NW_I; i += 1024)
        bm[i] = (i == NW_I - 1) ? 0x80000000u : 0u;  // root marked
    if (tid < LVBM_W) lvbm[tid] = 0u;
    if (tid < LEVELS) nl[tid] = (tid == LEVELS - 1) ? 1 : 0;
    if (tid == 0) { lvl_list[(LEVELS - 1) * LVL_CAP] = WIDTH - 1; ovf = 0; }
    __syncthreads();

    // ---- Top-down marking: one pass per level over its worklist ----
    for (int l = LEVELS - 1; l >= 0; --l) {
        const int n = nl[l];   // final: additions to level l only come from
                               // higher levels, all expanded before this point
        const int nn = (n < LVL_CAP) ? n : LVL_CAP;
        for (int i = tid; i < nn; i += 1024) {
            int4 c = __ldg(&child4[l * WIDTH + lvl_list[l * LVL_CAP + i]]);
            #pragma unroll
            for (int k = 0; k < 4; ++k) {
                int ch = (k == 0) ? c.x : (k == 1) ? c.y : (k == 2) ? c.z : c.w;
                if (ch < LEAVES) {
                    int var = ch & (NUM_VARS - 1);
                    atomicOr(&lvbm[var >> 5], 1u << (var & 31));
                } else {
                    int m = ch - LEAVES;
                    uint32_t bit = 1u << (m & 31);
                    uint32_t old = atomicOr(&bm[m >> 5], bit);
                    if (!(old & bit)) {
                        int lc  = m >> 12;
                        int pos = atomicAdd(&nl[lc], 1);
                        if (pos < LVL_CAP) lvl_list[lc * LVL_CAP + pos] = m & (WIDTH - 1);
                        else ovf = 1;
                    }
                }
            }
        }
        __syncthreads();
    }

    // ---- Needed-var compaction (64 words; tiny) ----
    if (tid < LVBM_W) lpref[tid] = __popc(lvbm[tid]);
    __syncthreads();
    if (tid == 0) {
        int a = 0;
        for (int i = 0; i < LVBM_W; ++i) { int t = lpref[i]; lpref[i] = a; a += t; }
        lpref[LVBM_W] = a;
    }
    __syncthreads();
    if (tid < LVBM_W) {
        uint32_t m = lvbm[tid];
        int base = lpref[tid];
        while (m) {
            int b = __ffs(m) - 1; m &= m - 1;
            int var = (tid << 5) + b;
            varpos[var] = base;
            g_varlist[base] = var;
            ++base;
        }
    }

    // ---- Interior compaction: exclusive prefix over word popcounts ----
    for (int i = tid; i < NW_I; i += 1024) pref[i] = __popc(bm[i]);
    __syncthreads();

    if (tid < NGROUPS_I) {
        int s = 0;
        #pragma unroll
        for (int k = 0; k < 32; ++k) s += pref[tid * 32 + k];
        gsum[tid] = s;
    }
    __syncthreads();
    if (tid == 0) {
        int a = 0;
        for (int g = 0; g < NGROUPS_I; ++g) { int t = gsum[g]; gsum[g] = a; a += t; }
        gsum[NGROUPS_I] = a;
    }
    __syncthreads();

    const int wid = tid >> 5, lane = tid & 31;
    for (int g = wid; g < NGROUPS_I; g += 32) {
        int v  = pref[g * 32 + lane];
        int xs = v;
        #pragma unroll
        for (int o = 1; o < 32; o <<= 1) {
            int y = __shfl_up_sync(0xFFFFFFFFu, xs, o);
            if (lane >= o) xs += y;
        }
        pref[g * 32 + lane] = gsum[g] + xs - v;
    }
    __syncthreads();

    const int n_int = gsum[NGROUPS_I];

    // ---- Pass 1: slot ids (slot order == node-index order; root = last) ----
    for (int i = tid; i < NW_I; i += 1024) {
        uint32_t m = bm[i];
        int base = pref[i];
        while (m) {
            int b = __ffs(m) - 1; m &= m - 1;
            g_slot[(i << 5) + b] = base++;
        }
    }
    __syncthreads();

    // ---- Pass 2: program emission ----
    for (int i = tid; i < NW_I; i += 1024) {
        uint32_t m = bm[i];
        int base = pref[i];
        while (m) {
            int b = __ffs(m) - 1; m &= m - 1;
            int node = (i << 5) + b;
            int s = base++;
            if (s < PROG_CAP) {
                int4 c = __ldg(&child4[node]);
                int op = __ldg(&op_type[node]);
                int e[4];
                #pragma unroll
                for (int k = 0; k < 4; ++k) {
                    int ch = (k == 0) ? c.x : (k == 1) ? c.y : (k == 2) ? c.z : c.w;
                    if (ch < LEAVES)
                        e[k] = (varpos[ch & (NUM_VARS - 1)] << 1) | (ch >= NUM_VARS ? 1 : 0);
                    else
                        e[k] = LEAVES + min(g_slot[ch - LEAVES], ICAP - 1);
                }
                g_prog[s] = make_int4(e[0] | (op << 30), e[1], e[2], e[3]);
            }
        }
    }

    if (tid == 0) {
        g_hdr[0] = n_int;
        for (int l = 0; l < LEVELS; ++l) g_hdr[1 + l] = pref[l * LVL_WORDS];
        g_hdr[1 + LEVELS] = n_int;
        g_hdr[14] = lpref[LVBM_W];   // nv
        g_hdr[15] = ovf;
    }
}

// ============================================================================
// Phase B: one warp per batch element. Up-front independent gather of the
// ~440 needed vars into smem (off the dependent chain), then a pure-LDS
// 12-level evaluation chain.
// ============================================================================
__global__ void __launch_bounds__(TB_B, 1)
eval_kernel(const float* __restrict__ x,    // [B, NUM_VARS]
            float*       __restrict__ out)  // [B]
{
    __shared__ int4  sprog[ICAP];           // 12 KB
    __shared__ float ival[EPB * ICAP];      // 12 KB
    __shared__ float slv[EPB * VCAP];       // 16 KB gathered leaf vars
    __shared__ int   svl[VCAP];             // 4 KB var list
    __shared__ int   shdr[20];

    const int tid = threadIdx.x;

    if (tid < 20) shdr[tid] = g_hdr[tid];
    {
        const int n_int0 = g_hdr[0];
        const int nv0    = g_hdr[14];
        const int nc = (n_int0 < ICAP) ? n_int0 : ICAP;
        for (int j = tid; j < nc; j += TB_B) sprog[j] = g_prog[j];
        const int nvc = (nv0 < VCAP) ? nv0 : VCAP;
        for (int s = tid; s < nvc; s += TB_B) svl[s] = g_varlist[s];
    }
    __syncthreads();

    const int n_int = shdr[0];
    const int nv    = shdr[14];
    const int ovf   = shdr[15];
    const int we = tid >> 5, lane = tid & 31;
    const int b = blockIdx.x * EPB + we;
    const float* xr = x + (size_t)b * NUM_VARS;
    float* iv = ival + we * ICAP;
    float* lv = slv  + we * VCAP;

    // -- Gather: independent, partially coalesced (sorted var list) --
    for (int s = lane; s < nv && s < VCAP; s += 32)
        lv[s] = __ldg(&xr[svl[s]]);
    __syncwarp();

    // -- Pure-LDS level chain --
    #pragma unroll 1
    for (int l = 0; l < LEVELS; ++l) {
        const int e0 = shdr[1 + l], e1 = shdr[2 + l];
        for (int j = e0 + lane; j < e1; j += 32) {
            int4 e = (j < ICAP) ? sprog[j] : __ldg(&g_prog[j]);
            int r0 = e.x & 0x3FFFFFFF;
            int op = (unsigned)e.x >> 30;
            float a, c2, d, f;
            {
                int r = r0;
                a  = (r < LEAVES) ? ((r & 1) ? 1.0f - lv[min(r >> 1, VCAP - 1)]
                                             : lv[min(r >> 1, VCAP - 1)])
                                  : iv[r - LEAVES];
                r = e.y;
                c2 = (r < LEAVES) ? ((r & 1) ? 1.0f - lv[min(r >> 1, VCAP - 1)]
                                             : lv[min(r >> 1, VCAP - 1)])
                                  : iv[r - LEAVES];
                r = e.z;
                d  = (r < LEAVES) ? ((r & 1) ? 1.0f - lv[min(r >> 1, VCAP - 1)]
                                             : lv[min(r >> 1, VCAP - 1)])
                                  : iv[r - LEAVES];
                r = e.w;
                f  = (r < LEAVES) ? ((r & 1) ? 1.0f - lv[min(r >> 1, VCAP - 1)]
                                             : lv[min(r >> 1, VCAP - 1)])
                                  : iv[r - LEAVES];
            }
            float r = op ? (a + c2) + (d + f) : (a * c2) * (d * f);
            if (j < ICAP) iv[j] = r;
        }
        __syncwarp();
    }

    // Any overflow leaves out poisoned -> loud failure, never silent.
    if (lane == 0 && n_int <= ICAP && nv <= VCAP && !ovf)
        out[b] = iv[n_int - 1];
}

// ============================================================================
extern "C" void kernel_launch(void* const* d_in, const int* in_sizes, int n_in,
                              void* d_out, int out_size)
{
    const float* x       = (const float*)d_in[0];  // [1024, 2048] f32
    const int4*  child4  = (const int4*) d_in[1];  // [12, 4096, 4] i32
    const int*   op_type = (const int*)  d_in[2];  // [12, 4096] i32
    float*       out     = (float*)d_out;          // [1024] f32

    prune_kernel<<<1, 1024>>>(child4, op_type);
    eval_kernel<<<GRID_B, TB_B>>>(x, out);
}

// round 16
// speedup vs baseline: 1.1416x; 1.1416x over previous
#include <cuda_runtime.h>
#include <cstdint>

// ---- Problem constants ----
#define NBATCH    1024
#define NUM_VARS  2048
#define LEAVES    4096
#define LEVELS    12
#define WIDTH     4096
#define NODES     (LEVELS * WIDTH)          // 49152
#define NW_I      (NODES / 32)              // 1536
#define LVL_WORDS (WIDTH / 32)              // 128
#define NGROUPS_I (NW_I / 32)               // 48
#define LVBM_W    (NUM_VARS / 32)           // 64

// ---- Capacities (expected: ~160 interior, ~440 vars, <=91/level) ----
#define ICAP      768      // interior slots (overflow -> loud fail)
#define VCAP      1024     // gathered-var slots (overflow -> loud fail)
#define PROG_CAP  8192
#define LVL_CAP   512      // per-level worklist (overflow -> flag -> loud fail)

// ---- Eval config ----
#define EPB    4
#define TB_B   (EPB * 32)              // 128 threads
#define GRID_B (NBATCH / EPB)          // 256 CTAs

// ---- Device-global scratch ----
__device__ int  g_slot[NODES];
__device__ int4 g_prog[PROG_CAP];
__device__ int  g_varlist[NUM_VARS + 256];
__device__ int  g_hdr[20];  // [0]=n_int [1..13]=offs [14]=nv [15]=ovf [16]=nv_pad

// Operand encoding:
//   ref < 4096 : leaf.  pos = ref>>1 into gathered vars; complement if (ref&1)
//   ref >= 4096: interior slot = ref - 4096
//   op (0=AND,1=OR) in bit 30 of .x

// ============================================================================
// Phase A (1 CTA): worklist reachability + var-list + compact program.
// ============================================================================
__global__ void __launch_bounds__(1024, 1)
prune_kernel(const int4* __restrict__ child4,   // [NODES]
             const int*  __restrict__ op_type)  // [NODES]
{
    __shared__ uint32_t bm[NW_I];                    // 6 KB
    __shared__ int      pref[NW_I];                  // 6 KB
    __shared__ int      gsum[NGROUPS_I + 1];
    __shared__ int      lvl_list[LEVELS * LVL_CAP];  // 24 KB
    __shared__ int      nl[LEVELS];
    __shared__ uint32_t lvbm[LVBM_W];                // needed vars
    __shared__ int      lpref[LVBM_W + 1];
    __shared__ int      varpos[NUM_VARS];            // 8 KB
    __shared__ int      ovf;

    const int tid = threadIdx.x;

    for (int i = tid; i < NW_I; i += 1024)
        bm[i] = (i == NW_I - 1) ? 0x80000000u : 0u;  // root marked
    if (tid < LVBM_W) lvbm[tid] = 0u;
    if (tid < LEVELS) nl[tid] = (tid == LEVELS - 1) ? 1 : 0;
    if (tid == 0) { lvl_list[(LEVELS - 1) * LVL_CAP] = WIDTH - 1; ovf = 0; }
    __syncthreads();

    // ---- Top-down marking: one pass per level over its worklist.
    //      Children are strictly lower-level, so nl[l] is final here. ----
    for (int l = LEVELS - 1; l >= 0; --l) {
        const int n = nl[l];
        const int nn = (n < LVL_CAP) ? n : LVL_CAP;
        for (int i = tid; i < nn; i += 1024) {
            int4 c = __ldg(&child4[l * WIDTH + lvl_list[l * LVL_CAP + i]]);
            #pragma unroll
            for (int k = 0; k < 4; ++k) {
                int ch = (k == 0) ? c.x : (k == 1) ? c.y : (k == 2) ? c.z : c.w;
                if (ch < LEAVES) {
                    int var = ch & (NUM_VARS - 1);
                    atomicOr(&lvbm[var >> 5], 1u << (var & 31));
                } else {
                    int m = ch - LEAVES;
                    uint32_t bit = 1u << (m & 31);
                    uint32_t old = atomicOr(&bm[m >> 5], bit);
                    if (!(old & bit)) {
                        int lc  = m >> 12;
                        int pos = atomicAdd(&nl[lc], 1);
                        if (pos < LVL_CAP) lvl_list[lc * LVL_CAP + pos] = m & (WIDTH - 1);
                        else ovf = 1;
                    }
                }
            }
        }
        __syncthreads();
    }

    // ---- Needed-var compaction ----
    if (tid < LVBM_W) lpref[tid] = __popc(lvbm[tid]);
    __syncthreads();
    if (tid == 0) {
        int a = 0;
        for (int i = 0; i < LVBM_W; ++i) { int t = lpref[i]; lpref[i] = a; a += t; }
        lpref[LVBM_W] = a;
    }
    __syncthreads();
    if (tid < LVBM_W) {
        uint32_t m = lvbm[tid];
        int base = lpref[tid];
        while (m) {
            int b = __ffs(m) - 1; m &= m - 1;
            int var = (tid << 5) + b;
            varpos[var] = base;
            g_varlist[base] = var;
            ++base;
        }
    }
    __syncthreads();

    // ---- Pad var list to a multiple of 256 (enables 8-wide MLP gather) ----
    {
        const int nv = lpref[LVBM_W];          // >= 1 always
        const int nv_pad = (nv + 255) & ~255;
        if (tid < nv_pad - nv) g_varlist[nv + tid] = g_varlist[0];
        if (tid == 0) g_hdr[16] = (nv_pad <= VCAP) ? nv_pad : 0;
    }

    // ---- Interior compaction: exclusive prefix over word popcounts ----
    for (int i = tid; i < NW_I; i += 1024) pref[i] = __popc(bm[i]);
    __syncthreads();

    if (tid < NGROUPS_I) {
        int s = 0;
        #pragma unroll
        for (int k = 0; k < 32; ++k) s += pref[tid * 32 + k];
        gsum[tid] = s;
    }
    __syncthreads();
    if (tid == 0) {
        int a = 0;
        for (int g = 0; g < NGROUPS_I; ++g) { int t = gsum[g]; gsum[g] = a; a += t; }
        gsum[NGROUPS_I] = a;
    }
    __syncthreads();

    const int wid = tid >> 5, lane = tid & 31;
    for (int g = wid; g < NGROUPS_I; g += 32) {
        int v  = pref[g * 32 + lane];
        int xs = v;
        #pragma unroll
        for (int o = 1; o < 32; o <<= 1) {
            int y = __shfl_up_sync(0xFFFFFFFFu, xs, o);
            if (lane >= o) xs += y;
        }
        pref[g * 32 + lane] = gsum[g] + xs - v;
    }
    __syncthreads();

    const int n_int = gsum[NGROUPS_I];

    // ---- Pass 1: slot ids (slot order == node-index order; root = last) ----
    for (int i = tid; i < NW_I; i += 1024) {
        uint32_t m = bm[i];
        int base = pref[i];
        while (m) {
            int b = __ffs(m) - 1; m &= m - 1;
            g_slot[(i << 5) + b] = base++;
        }
    }
    __syncthreads();

    // ---- Pass 2: program emission ----
    for (int i = tid; i < NW_I; i += 1024) {
        uint32_t m = bm[i];
        int base = pref[i];
        while (m) {
            int b = __ffs(m) - 1; m &= m - 1;
            int node = (i << 5) + b;
            int s = base++;
            if (s < PROG_CAP) {
                int4 c = __ldg(&child4[node]);
                int op = __ldg(&op_type[node]);
                int e[4];
                #pragma unroll
                for (int k = 0; k < 4; ++k) {
                    int ch = (k == 0) ? c.x : (k == 1) ? c.y : (k == 2) ? c.z : c.w;
                    if (ch < LEAVES)
                        e[k] = (varpos[ch & (NUM_VARS - 1)] << 1) | (ch >= NUM_VARS ? 1 : 0);
                    else
                        e[k] = LEAVES + min(g_slot[ch - LEAVES], ICAP - 1);
                }
                g_prog[s] = make_int4(e[0] | (op << 30), e[1], e[2], e[3]);
            }
        }
    }

    if (tid == 0) {
        g_hdr[0] = n_int;
        for (int l = 0; l < LEVELS; ++l) g_hdr[1 + l] = pref[l * LVL_WORDS];
        g_hdr[1 + LEVELS] = n_int;
        g_hdr[14] = lpref[LVBM_W];   // nv
        g_hdr[15] = ovf;
    }
}

// ============================================================================
// Phase B: one warp per batch element. 8-wide-MLP gather of needed vars into
// smem, then a pure-LDS 12-level evaluation chain.
// ============================================================================
__global__ void __launch_bounds__(TB_B, 1)
eval_kernel(const float* __restrict__ x,    // [B, NUM_VARS]
            float*       __restrict__ out)  // [B]
{
    __shared__ int4  sprog[ICAP];           // 12 KB
    __shared__ float ival[EPB * ICAP];      // 12 KB
    __shared__ float slv[EPB * VCAP];       // 16 KB gathered leaf vars
    __shared__ int   svl[VCAP];             // 4 KB var list (padded)
    __shared__ int   shdr[20];

    const int tid = threadIdx.x;

    if (tid < 20) shdr[tid] = g_hdr[tid];
    {
        const int n_int0 = g_hdr[0];
        const int nvp0   = g_hdr[16];
        const int nc = (n_int0 < ICAP) ? n_int0 : ICAP;
        for (int j = tid; j < nc; j += TB_B) sprog[j] = g_prog[j];
        for (int s = tid; s < nvp0; s += TB_B) svl[s] = g_varlist[s];
    }
    __syncthreads();

    const int n_int = shdr[0];
    const int nv    = shdr[14];
    const int ovf   = shdr[15];
    const int nvp   = shdr[16];              // multiple of 256; 0 on overflow
    const int we = tid >> 5, lane = tid & 31;
    const int b = blockIdx.x * EPB + we;
    const float* xr = x + (size_t)b * NUM_VARS;
    float* iv = ival + we * ICAP;
    float* lv = slv  + we * VCAP;

    // -- Gather with explicit 8-deep MLP (nvp is a multiple of 256) --
    for (int s = lane; s < nvp; s += 256) {
        float v0 = __ldg(&xr[svl[s      ]]);
        float v1 = __ldg(&xr[svl[s +  32]]);
        float v2 = __ldg(&xr[svl[s +  64]]);
        float v3 = __ldg(&xr[svl[s +  96]]);
        float v4 = __ldg(&xr[svl[s + 128]]);
        float v5 = __ldg(&xr[svl[s + 160]]);
        float v6 = __ldg(&xr[svl[s + 192]]);
        float v7 = __ldg(&xr[svl[s + 224]]);
        lv[s      ] = v0;  lv[s +  32] = v1;
        lv[s +  64] = v2;  lv[s +  96] = v3;
        lv[s + 128] = v4;  lv[s + 160] = v5;
        lv[s + 192] = v6;  lv[s + 224] = v7;
    }
    __syncwarp();

    // -- Pure-LDS level chain --
    #pragma unroll 1
    for (int l = 0; l < LEVELS; ++l) {
        const int e0 = shdr[1 + l], e1 = shdr[2 + l];
        for (int j = e0 + lane; j < e1; j += 32) {
            int4 e = (j < ICAP) ? sprog[j] : __ldg(&g_prog[j]);
            int r0 = e.x & 0x3FFFFFFF;
            int op = (unsigned)e.x >> 30;
            float a, c2, d, f;
            {
                int r = r0;
                a  = (r < LEAVES) ? ((r & 1) ? 1.0f - lv[min(r >> 1, VCAP - 1)]
                                             : lv[min(r >> 1, VCAP - 1)])
                                  : iv[r - LEAVES];
                r = e.y;
                c2 = (r < LEAVES) ? ((r & 1) ? 1.0f - lv[min(r >> 1, VCAP - 1)]
                                             : lv[min(r >> 1, VCAP - 1)])
                                  : iv[r - LEAVES];
                r = e.z;
                d  = (r < LEAVES) ? ((r & 1) ? 1.0f - lv[min(r >> 1, VCAP - 1)]
                                             : lv[min(r >> 1, VCAP - 1)])
                                  : iv[r - LEAVES];
                r = e.w;
                f  = (r < LEAVES) ? ((r & 1) ? 1.0f - lv[min(r >> 1, VCAP - 1)]
                                             : lv[min(r >> 1, VCAP - 1)])
                                  : iv[r - LEAVES];
            }
            float r = op ? (a + c2) + (d + f) : (a * c2) * (d * f);
            if (j < ICAP) iv[j] = r;
        }
        __syncwarp();
    }

    // Any overflow leaves out poisoned -> loud failure, never silent.
    if (lane == 0 && n_int <= ICAP && nv <= VCAP && nvp > 0 && !ovf)
        out[b] = iv[n_int - 1];
}

// ============================================================================
extern "C" void kernel_launch(void* const* d_in, const int* in_sizes, int n_in,
                              void* d_out, int out_size)
{
    const float* x       = (const float*)d_in[0];  // [1024, 2048] f32
    const int4*  child4  = (const int4*) d_in[1];  // [12, 4096, 4] i32
    const int*   op_type = (const int*)  d_in[2];  // [12, 4096] i32
    float*       out     = (float*)d_out;          // [1024] f32

    prune_kernel<<<1, 1024>>>(child4, op_type);
    eval_kernel<<<GRID_B, TB_B>>>(x, out);
}